// round 2
// baseline (speedup 1.0000x reference)
#include <cuda_runtime.h>

// Flash attention, fp32 SIMT (round 0 baseline).
// B=2, S_q=2048, H=16, D=128, S_kv = W*S = 8192 (derived from in_sizes).
// Layouts: q [B,Sq,H,D], k/v [B,Skv,H,D], out [B,Sq,H,D] (all fp32).
// The reference's ring/online-softmax loop equals exact full softmax attention,
// so a single flash pass reproduces it to ~1e-6.

namespace {

constexpr int B  = 2;
constexpr int S  = 2048;
constexpr int H  = 16;
constexpr int DH = 128;

constexpr int BM = 64;    // Q rows per CTA
constexpr int BN = 64;    // KV rows per tile
constexpr int NT = 256;   // threads per CTA (16 x 16)

// smem row strides (floats), padded for bank-conflict avoidance
constexpr int QT_S = 65;   // Qt[d][m], transposed
constexpr int KT_S = 65;   // Kt[d][n], transposed
constexpr int VS_S = 132;  // Vs[n][d], natural (16B-aligned rows)
constexpr int PS_S = 65;   // Ps[m][n]

constexpr int SMEM_FLOATS = DH * QT_S + DH * KT_S + BN * VS_S + BM * PS_S;
constexpr int SMEM_BYTES  = SMEM_FLOATS * 4;   // 116,992 B

constexpr float SCALE = 0.08838834764831845f;  // 1/sqrt(128)

__global__ __launch_bounds__(NT, 1)
void fa_fp32(const float* __restrict__ qg, const float* __restrict__ kg,
             const float* __restrict__ vg, float* __restrict__ out, int skv)
{
    extern __shared__ float sm[];
    float* Qt = sm;                       // [DH][QT_S]
    float* Kt = Qt + DH * QT_S;           // [DH][KT_S]
    float* Vs = Kt + DH * KT_S;           // [BN][VS_S]
    float* Ps = Vs + BN * VS_S;           // [BM][PS_S]

    const int tid = threadIdx.x;
    const int tx  = tid & 15;             // col group
    const int ty  = tid >> 4;             // row group
    const int qtile = blockIdx.x;
    const int b = blockIdx.y >> 4;        // H == 16
    const int h = blockIdx.y & 15;

    const size_t rs = (size_t)H * DH;     // row stride in floats (2048)
    const float* qp = qg + ((size_t)b * S + (size_t)qtile * BM) * rs + (size_t)h * DH;
    const float* kp = kg + (size_t)b * skv * rs + (size_t)h * DH;
    const float* vp = vg + (size_t)b * skv * rs + (size_t)h * DH;

    // ---- load Q tile once, transposed into Qt[d][m] ----
    #pragma unroll
    for (int t = 0; t < (BM * DH / 4) / NT; t++) {     // 8 iters
        int idx = tid + t * NT;
        int row = idx >> 5;                            // 0..63
        int d4  = (idx & 31) * 4;                      // 0..124 step 4
        float4 f = *reinterpret_cast<const float4*>(qp + (size_t)row * rs + d4);
        Qt[(d4 + 0) * QT_S + row] = f.x;
        Qt[(d4 + 1) * QT_S + row] = f.y;
        Qt[(d4 + 2) * QT_S + row] = f.z;
        Qt[(d4 + 3) * QT_S + row] = f.w;
    }

    // per-thread online-softmax state
    float m_run[4], l_run[4], oacc[4][8];
    #pragma unroll
    for (int i = 0; i < 4; i++) {
        m_run[i] = -3.0e38f;
        l_run[i] = 0.0f;
        #pragma unroll
        for (int j = 0; j < 8; j++) oacc[i][j] = 0.0f;
    }

    const int ntiles = skv / BN;
    for (int tile = 0; tile < ntiles; tile++) {
        const float* kt = kp + (size_t)tile * BN * rs;
        const float* vt = vp + (size_t)tile * BN * rs;

        // ---- stage K (transposed) and V (natural) ----
        #pragma unroll
        for (int t = 0; t < (BN * DH / 4) / NT; t++) { // 8 iters
            int idx = tid + t * NT;
            int row = idx >> 5;
            int d4  = (idx & 31) * 4;
            float4 f = *reinterpret_cast<const float4*>(kt + (size_t)row * rs + d4);
            Kt[(d4 + 0) * KT_S + row] = f.x;
            Kt[(d4 + 1) * KT_S + row] = f.y;
            Kt[(d4 + 2) * KT_S + row] = f.z;
            Kt[(d4 + 3) * KT_S + row] = f.w;
            float4 g = *reinterpret_cast<const float4*>(vt + (size_t)row * rs + d4);
            *reinterpret_cast<float4*>(Vs + row * VS_S + d4) = g;
        }
        __syncthreads();

        // ---- S = Q @ K^T (64x64, k over 128) ----
        float acc[4][4];
        #pragma unroll
        for (int i = 0; i < 4; i++)
            #pragma unroll
            for (int j = 0; j < 4; j++) acc[i][j] = 0.0f;

        #pragma unroll 8
        for (int kk = 0; kk < DH; kk++) {
            float qf[4], kf[4];
            #pragma unroll
            for (int i = 0; i < 4; i++) qf[i] = Qt[kk * QT_S + ty + 16 * i];
            #pragma unroll
            for (int j = 0; j < 4; j++) kf[j] = Kt[kk * KT_S + tx + 16 * j];
            #pragma unroll
            for (int i = 0; i < 4; i++)
                #pragma unroll
                for (int j = 0; j < 4; j++)
                    acc[i][j] = fmaf(qf[i], kf[j], acc[i][j]);
        }

        // ---- online softmax; write P to smem ----
        #pragma unroll
        for (int i = 0; i < 4; i++) {
            float mx = -3.0e38f;
            #pragma unroll
            for (int j = 0; j < 4; j++) {
                acc[i][j] *= SCALE;
                mx = fmaxf(mx, acc[i][j]);
            }
            // row max across the 16 threads of this row group (lanes share bit4=ty&1)
            #pragma unroll
            for (int o = 8; o >= 1; o >>= 1)
                mx = fmaxf(mx, __shfl_xor_sync(0xffffffffu, mx, o));

            float mnew  = fmaxf(m_run[i], mx);
            float alpha = __expf(m_run[i] - mnew);

            float ls = 0.0f;
            #pragma unroll
            for (int j = 0; j < 4; j++) {
                float p = __expf(acc[i][j] - mnew);
                Ps[(ty + 16 * i) * PS_S + tx + 16 * j] = p;
                ls += p;
            }
            #pragma unroll
            for (int o = 8; o >= 1; o >>= 1)
                ls += __shfl_xor_sync(0xffffffffu, ls, o);

            l_run[i] = l_run[i] * alpha + ls;
            m_run[i] = mnew;
            #pragma unroll
            for (int j = 0; j < 8; j++) oacc[i][j] *= alpha;
        }
        __syncthreads();

        // ---- O += P @ V (64x128, n over 64) ----
        #pragma unroll 4
        for (int n = 0; n < BN; n++) {
            float pf[4], vf[8];
            #pragma unroll
            for (int i = 0; i < 4; i++) pf[i] = Ps[(ty + 16 * i) * PS_S + n];
            #pragma unroll
            for (int j = 0; j < 8; j++) vf[j] = Vs[n * VS_S + tx + 16 * j];
            #pragma unroll
            for (int i = 0; i < 4; i++)
                #pragma unroll
                for (int j = 0; j < 8; j++)
                    oacc[i][j] = fmaf(pf[i], vf[j], oacc[i][j]);
        }
        __syncthreads();   // PV reads done before next tile overwrites smem
    }

    // ---- epilogue: normalize and store ----
    float* op = out + ((size_t)b * S + (size_t)qtile * BM) * rs + (size_t)h * DH;
    #pragma unroll
    for (int i = 0; i < 4; i++) {
        float inv = 1.0f / l_run[i];
        #pragma unroll
        for (int j = 0; j < 8; j++)
            op[(size_t)(ty + 16 * i) * rs + tx + 16 * j] = oacc[i][j] * inv;
    }
}

} // namespace

extern "C" void kernel_launch(void* const* d_in, const int* in_sizes, int n_in,
                              void* d_out, int out_size)
{
    const float* q = (const float*)d_in[0];
    const float* k = (const float*)d_in[1];
    const float* v = (const float*)d_in[2];
    float* out = (float*)d_out;

    // k is [B, Skv, H, D] -> derive Skv (W*S) from element count
    const int skv = in_sizes[1] / (B * H * DH);

    cudaFuncSetAttribute(fa_fp32, cudaFuncAttributeMaxDynamicSharedMemorySize, SMEM_BYTES);

    dim3 grid(S / BM, B * H);
    fa_fp32<<<grid, NT, SMEM_BYTES>>>(q, k, v, out, skv);
}

// round 3
// speedup vs baseline: 1.1102x; 1.1102x over previous
#include <cuda_runtime.h>
#include <cstdint>

// Flash attention, fp32 SIMT, round 2:
//  - fma.rn.f32x2 packed FMAs (2 FLOP/instr) everywhere in both GEMMs
//  - natural row-major smem tiles, all fragment loads LDS.128/LDS.64
//  - QK^T pairs over k; P@V pairs over d with a pair-duplicated P buffer
//  - cp.async double-buffered K/V staging (overlap LDG with compute)

namespace {

constexpr int B  = 2;
constexpr int S  = 2048;
constexpr int H  = 16;
constexpr int DH = 128;

constexpr int BM = 64;
constexpr int BN = 64;
constexpr int NT = 256;

constexpr int TS = 132;                 // row stride (floats) for all tiles
constexpr int TILE_F = 64 * TS;         // 8448 floats per 64-row tile
// Qs | Ks[2] | Vs[2] | Psd  -> 6 tiles
constexpr int SMEM_BYTES = 6 * TILE_F * 4;   // 202,752 B

constexpr float SCALE = 0.08838834764831845f;  // 1/sqrt(128)

using ull = unsigned long long;

__device__ __forceinline__ ull fma2(ull a, ull b, ull c) {
    ull d;
    asm("fma.rn.f32x2 %0, %1, %2, %3;" : "=l"(d) : "l"(a), "l"(b), "l"(c));
    return d;
}
__device__ __forceinline__ ull mul2(ull a, ull b) {
    ull d;
    asm("mul.rn.f32x2 %0, %1, %2;" : "=l"(d) : "l"(a), "l"(b));
    return d;
}
__device__ __forceinline__ ull pack2(float x, float y) {
    ull r;
    asm("mov.b64 %0, {%1, %2};" : "=l"(r) : "f"(x), "f"(y));
    return r;
}
__device__ __forceinline__ void unpack2(ull v, float& lo, float& hi) {
    asm("mov.b64 {%0, %1}, %2;" : "=f"(lo), "=f"(hi) : "l"(v));
}
__device__ __forceinline__ void cpasync16(uint32_t saddr, const void* gaddr) {
    asm volatile("cp.async.cg.shared.global [%0], [%1], 16;\n"
                 :: "r"(saddr), "l"(gaddr));
}

__global__ __launch_bounds__(NT, 1)
void fa_fp32(const float* __restrict__ qg, const float* __restrict__ kg,
             const float* __restrict__ vg, float* __restrict__ out, int skv)
{
    extern __shared__ float sm[];
    float* Qs  = sm;                    // [64][TS]
    float* Ks  = sm + TILE_F;           // [2][64][TS]
    float* Vs  = sm + 3 * TILE_F;       // [2][64][TS]
    float* Psd = sm + 5 * TILE_F;       // [64][TS], entry pair (p,p) at [m][2n]

    const int tid = threadIdx.x;
    const int tx  = tid & 15;
    const int ty  = tid >> 4;
    const int qtile = blockIdx.x;
    const int b = blockIdx.y >> 4;      // H == 16
    const int h = blockIdx.y & 15;

    const size_t rs = (size_t)H * DH;   // 2048 floats
    const float* qp = qg + ((size_t)b * S + (size_t)qtile * BM) * rs + (size_t)h * DH;
    const float* kp = kg + (size_t)b * skv * rs + (size_t)h * DH;
    const float* vp = vg + (size_t)b * skv * rs + (size_t)h * DH;

    const uint32_t sKb = (uint32_t)__cvta_generic_to_shared(Ks);
    const uint32_t sVb = (uint32_t)__cvta_generic_to_shared(Vs);

    // ---- load Q tile once (natural layout, float4 copy) ----
    #pragma unroll
    for (int t = 0; t < (BM * DH / 4) / NT; t++) {   // 8 iters
        int idx = tid + t * NT;
        int row = idx >> 5;
        int d4  = (idx & 31) * 4;
        float4 f = *reinterpret_cast<const float4*>(qp + (size_t)row * rs + d4);
        *reinterpret_cast<float4*>(Qs + row * TS + d4) = f;
    }

    // ---- prefetch tile 0 into buffer 0 via cp.async ----
    {
        const float* kt = kp;
        const float* vt = vp;
        #pragma unroll
        for (int t = 0; t < 8; t++) {
            int idx = tid + t * NT;
            int row = idx >> 5;
            int d4  = (idx & 31) * 4;
            uint32_t so = (uint32_t)((row * TS + d4) * 4);
            cpasync16(sKb + so, kt + (size_t)row * rs + d4);
            cpasync16(sVb + so, vt + (size_t)row * rs + d4);
        }
        asm volatile("cp.async.commit_group;\n" ::: "memory");
    }

    // per-thread softmax state: rows m_i = ty + 16*i
    float m_run[4], l_run[4];
    ull oacc2[4][4];                    // (m_i, d pair c): d = 8*tx + 2c, 2c+1
    #pragma unroll
    for (int i = 0; i < 4; i++) {
        m_run[i] = -3.0e38f;
        l_run[i] = 0.0f;
        #pragma unroll
        for (int c = 0; c < 4; c++) oacc2[i][c] = 0ull;
    }

    const int ntiles = skv / BN;
    for (int tile = 0; tile < ntiles; tile++) {
        const int cur = tile & 1;
        float* Kb = Ks + cur * TILE_F;
        float* Vb = Vs + cur * TILE_F;

        // prefetch next tile into the other buffer, then wait for current
        if (tile + 1 < ntiles) {
            const float* kt = kp + (size_t)(tile + 1) * BN * rs;
            const float* vt = vp + (size_t)(tile + 1) * BN * rs;
            uint32_t bufo = (uint32_t)((cur ^ 1) * TILE_F * 4);
            #pragma unroll
            for (int t = 0; t < 8; t++) {
                int idx = tid + t * NT;
                int row = idx >> 5;
                int d4  = (idx & 31) * 4;
                uint32_t so = bufo + (uint32_t)((row * TS + d4) * 4);
                cpasync16(sKb + so, kt + (size_t)row * rs + d4);
                cpasync16(sVb + so, vt + (size_t)row * rs + d4);
            }
            asm volatile("cp.async.commit_group;\n" ::: "memory");
            asm volatile("cp.async.wait_group 1;\n" ::: "memory");
        } else {
            asm volatile("cp.async.wait_group 0;\n" ::: "memory");
        }
        __syncthreads();

        // ---- S = Q @ K^T : dot-product style, FFMA2 pairs over k ----
        ull acc2[4][4];
        #pragma unroll
        for (int i = 0; i < 4; i++)
            #pragma unroll
            for (int j = 0; j < 4; j++) acc2[i][j] = 0ull;

        #pragma unroll 2
        for (int kk = 0; kk < DH; kk += 4) {
            ulonglong2 qv[4], kv[4];
            #pragma unroll
            for (int i = 0; i < 4; i++)
                qv[i] = *reinterpret_cast<const ulonglong2*>(Qs + (ty + 16 * i) * TS + kk);
            #pragma unroll
            for (int j = 0; j < 4; j++)
                kv[j] = *reinterpret_cast<const ulonglong2*>(Kb + (tx + 16 * j) * TS + kk);
            #pragma unroll
            for (int i = 0; i < 4; i++)
                #pragma unroll
                for (int j = 0; j < 4; j++) {
                    acc2[i][j] = fma2(qv[i].x, kv[j].x, acc2[i][j]);
                    acc2[i][j] = fma2(qv[i].y, kv[j].y, acc2[i][j]);
                }
        }

        // ---- online softmax; write duplicated-pair P ----
        #pragma unroll
        for (int i = 0; i < 4; i++) {
            float a[4];
            float mx = -3.0e38f;
            #pragma unroll
            for (int j = 0; j < 4; j++) {
                float lo, hi;
                unpack2(acc2[i][j], lo, hi);
                a[j] = (lo + hi) * SCALE;
                mx = fmaxf(mx, a[j]);
            }
            #pragma unroll
            for (int o = 8; o >= 1; o >>= 1)
                mx = fmaxf(mx, __shfl_xor_sync(0xffffffffu, mx, o));

            float mnew  = fmaxf(m_run[i], mx);
            float alpha = __expf(m_run[i] - mnew);

            float ls = 0.0f;
            #pragma unroll
            for (int j = 0; j < 4; j++) {
                float p = __expf(a[j] - mnew);
                int n = tx + 16 * j;
                *reinterpret_cast<float2*>(Psd + (ty + 16 * i) * TS + 2 * n) =
                    make_float2(p, p);
                ls += p;
            }
            #pragma unroll
            for (int o = 8; o >= 1; o >>= 1)
                ls += __shfl_xor_sync(0xffffffffu, ls, o);

            l_run[i] = l_run[i] * alpha + ls;
            m_run[i] = mnew;

            ull a2 = pack2(alpha, alpha);
            #pragma unroll
            for (int c = 0; c < 4; c++) oacc2[i][c] = mul2(oacc2[i][c], a2);
        }
        __syncthreads();   // P visible to all

        // ---- O += P @ V : FFMA2 pairs over d, P pairs broadcast-duplicated ----
        #pragma unroll 2
        for (int n2 = 0; n2 < BN; n2 += 2) {
            ulonglong2 pf[4];   // ((p_n2,p_n2),(p_n2+1,p_n2+1)) for row m_i
            #pragma unroll
            for (int i = 0; i < 4; i++)
                pf[i] = *reinterpret_cast<const ulonglong2*>(
                            Psd + (ty + 16 * i) * TS + 2 * n2);
            #pragma unroll
            for (int u = 0; u < 2; u++) {
                const float* vrow = Vb + (n2 + u) * TS + 8 * tx;
                ulonglong2 v0 = *reinterpret_cast<const ulonglong2*>(vrow);
                ulonglong2 v1 = *reinterpret_cast<const ulonglong2*>(vrow + 4);
                #pragma unroll
                for (int i = 0; i < 4; i++) {
                    ull p = u ? pf[i].y : pf[i].x;
                    oacc2[i][0] = fma2(p, v0.x, oacc2[i][0]);
                    oacc2[i][1] = fma2(p, v0.y, oacc2[i][1]);
                    oacc2[i][2] = fma2(p, v1.x, oacc2[i][2]);
                    oacc2[i][3] = fma2(p, v1.y, oacc2[i][3]);
                }
            }
        }
        __syncthreads();   // PV reads done before next tile overwrites Psd/buffers
    }

    // ---- epilogue: normalize and store (d = 8*tx + 0..7) ----
    float* op = out + ((size_t)b * S + (size_t)qtile * BM) * rs + (size_t)h * DH;
    #pragma unroll
    for (int i = 0; i < 4; i++) {
        float inv = 1.0f / l_run[i];
        float o0, o1, o2, o3, o4, o5, o6, o7;
        unpack2(oacc2[i][0], o0, o1);
        unpack2(oacc2[i][1], o2, o3);
        unpack2(oacc2[i][2], o4, o5);
        unpack2(oacc2[i][3], o6, o7);
        float* dst = op + (size_t)(ty + 16 * i) * rs + 8 * tx;
        *reinterpret_cast<float4*>(dst)     = make_float4(o0 * inv, o1 * inv, o2 * inv, o3 * inv);
        *reinterpret_cast<float4*>(dst + 4) = make_float4(o4 * inv, o5 * inv, o6 * inv, o7 * inv);
    }
}

} // namespace

extern "C" void kernel_launch(void* const* d_in, const int* in_sizes, int n_in,
                              void* d_out, int out_size)
{
    const float* q = (const float*)d_in[0];
    const float* k = (const float*)d_in[1];
    const float* v = (const float*)d_in[2];
    float* out = (float*)d_out;

    const int skv = in_sizes[1] / (B * H * DH);

    cudaFuncSetAttribute(fa_fp32, cudaFuncAttributeMaxDynamicSharedMemorySize, SMEM_BYTES);

    dim3 grid(S / BM, B * H);
    fa_fp32<<<grid, NT, SMEM_BYTES>>>(q, k, v, out, skv);
}